// round 17
// baseline (speedup 1.0000x reference)
#include <cuda_runtime.h>
#include <cuda_bf16.h>
#include <cstdint>

// ---------------- problem constants ----------------
#define B_    8
#define H_    56
#define W_    56
#define C_    192
#define NWH   14            // windows per side (56/4)
#define BW    1568          // total windows
#define MP    1664          // padded window rows = 13 * 128
#define IND   3072          // 4*4*192
#define HID   256
#define NCL   256
#define KSPL  6             // GEMM1 split-K (3072/6 = 512 per slice)

// ---------------- scratch (__device__ globals, zero-initialized) ----------
__device__ __nv_bfloat16 g_win[MP * IND];        // LN'd windows, bf16
__device__ __nv_bfloat16 g_W1T[HID * IND];       // W1^T  [256][3072]
__device__ __nv_bfloat16 g_W2T[IND * C_];        // W2^T  [3072][192]
__device__ __nv_bfloat16 g_vwb[NCL * C_];        // vote_w bf16 [256][192]
__device__ float         g_V[NCL * IND];         // V = (vote_w @ W2)/16  [256][3072]
__device__ float         g_part[KSPL * MP * HID];// GEMM1 split-K partials
__device__ uint32_t      g_incb[16 * NCL];       // include bits [16 words][256 clauses]

__device__ __forceinline__ float sigmoidf_(float x) { return 1.0f / (1.0f + __expf(-x)); }

__device__ __forceinline__ uint32_t s2u(const void* p) {
    uint32_t a;
    asm("{ .reg .u64 t; cvta.to.shared.u64 t, %1; cvt.u32.u64 %0, t; }" : "=r"(a) : "l"(p));
    return a;
}
#define CP_ASYNC16(dst, src) \
    asm volatile("cp.async.cg.shared.global [%0], [%1], 16;" :: "r"(dst), "l"(src))
#define CP_COMMIT() asm volatile("cp.async.commit_group;")
#define CP_WAIT(n)  asm volatile("cp.async.wait_group %0;" :: "n"(n))

// ---------------- fused K1: LN+roll+partition  AND  weight prep ---------------
#define NB_LN   3136           // 25088 pixels / 8 warps
#define SEG1 786432            // trW1:  3072*256
#define SEG2 1376256           // +trW2: 192*3072
#define SEG3 1507328           // +pack_inc: 256*512
#define SEGT 1556480           // +vote_w bf16 copy: 256*192
#define NB_PREP (SEGT / 256)   // 6080
__global__ void ln_prep_kernel(const float* __restrict__ x,
                               const float* __restrict__ gamma,
                               const float* __restrict__ beta,
                               const float* __restrict__ W1,
                               const float* __restrict__ W2,
                               const float* __restrict__ inc_w,
                               const float* __restrict__ vw) {
    if (blockIdx.x < NB_LN) {
        int gwarp = (blockIdx.x * blockDim.x + threadIdx.x) >> 5;
        int lane  = threadIdx.x & 31;
        const float* xr = x + (size_t)gwarp * C_;
        float v[6];
        float s = 0.f, ss = 0.f;
#pragma unroll
        for (int k = 0; k < 6; k++) {
            v[k] = xr[lane + 32 * k];
            s += v[k]; ss += v[k] * v[k];
        }
#pragma unroll
        for (int o = 16; o > 0; o >>= 1) {
            s  += __shfl_xor_sync(0xffffffffu, s, o);
            ss += __shfl_xor_sync(0xffffffffu, ss, o);
        }
        float mean = s * (1.0f / C_);
        float var  = ss * (1.0f / C_) - mean * mean;
        float inv  = rsqrtf(var + 1e-5f);

        int p = gwarp;
        int w = p % W_;
        int h = (p / W_) % H_;
        int b = p / (H_ * W_);
        int hr = (h + H_ - 2) % H_;
        int wr = (w + W_ - 2) % W_;
        int row  = b * (NWH * NWH) + (hr >> 2) * NWH + (wr >> 2);
        size_t base = (size_t)row * IND + ((hr & 3) * 4 + (wr & 3)) * C_;
#pragma unroll
        for (int k = 0; k < 6; k++) {
            int c = lane + 32 * k;
            g_win[base + c] = __float2bfloat16_rn((v[k] - mean) * inv * gamma[c] + beta[c]);
        }
    } else {
        int t = (blockIdx.x - NB_LN) * blockDim.x + threadIdx.x;
        if (t < SEG1) {                       // [3072][256] -> [256][3072]
            int k = t >> 8, n = t & 255;
            g_W1T[(size_t)n * IND + k] = __float2bfloat16_rn(W1[t]);
        } else if (t < SEG2) {                // [192][3072] -> [3072][192]
            int u = t - SEG1;
            int k = u / IND, n = u % IND;
            g_W2T[(size_t)n * C_ + k] = __float2bfloat16_rn(W2[u]);
        } else if (t < SEG3) {                // include bits: inc = (inc_w > 0)
            int u  = t - SEG2;
            int cl = u >> 9, j = u & 511;
            bool v = inc_w[(size_t)cl * 512 + j] > 0.0f;
            uint32_t m = __ballot_sync(0xffffffffu, v);
            if ((j & 31) == 0) g_incb[(j >> 5) * NCL + cl] = m;
        } else {                              // vote_w fp32 -> bf16 (same layout)
            int u = t - SEG3;
            g_vwb[u] = __float2bfloat16_rn(vw[u]);
        }
    }
}

// ---------------- bf16 mma.sync GEMM, 128x128 tile, 2-stage cp.async ----------
// Cf[m][n] = scale * sum_k A[m][k]*B[n][k]   (+ z*zStride offset for split-K)
__global__ void __launch_bounds__(256)
mma_gemm1(const __nv_bfloat16* __restrict__ A, int lda,
          const __nv_bfloat16* __restrict__ Bm, int ldb,
          float* __restrict__ Cf, int ldc, int kPerZ, int zStride, float scale) {
    __shared__ __nv_bfloat16 sA[2][128][40];
    __shared__ __nv_bfloat16 sB[2][128][40];
    int tid = threadIdx.x, wid = tid >> 5, lane = tid & 31;
    int bm = blockIdx.y * 128, bn = blockIdx.x * 128;
    int k0 = blockIdx.z * kPerZ;
    Cf += (size_t)blockIdx.z * zStride;

    int wm = (wid & 1) * 64;
    int wn = (wid >> 1) * 32;

    int i0 = tid,        r0 = i0 >> 2, c0 = (i0 & 3) * 8;
    int i1 = tid + 256,  r1 = i1 >> 2, c1 = (i1 & 3) * 8;
    const __nv_bfloat16* pA0 = A + (size_t)(bm + r0) * lda + c0;
    const __nv_bfloat16* pA1 = A + (size_t)(bm + r1) * lda + c1;
    const __nv_bfloat16* pB0 = Bm + (size_t)(bn + r0) * ldb + c0;
    const __nv_bfloat16* pB1 = Bm + (size_t)(bn + r1) * ldb + c1;

    float c[4][4][4];
#pragma unroll
    for (int i = 0; i < 4; i++)
#pragma unroll
        for (int j = 0; j < 4; j++)
#pragma unroll
            for (int q = 0; q < 4; q++) c[i][j][q] = 0.f;

    int iters = kPerZ >> 5;
    CP_ASYNC16(s2u(&sA[0][r0][c0]), pA0 + k0);
    CP_ASYNC16(s2u(&sA[0][r1][c1]), pA1 + k0);
    CP_ASYNC16(s2u(&sB[0][r0][c0]), pB0 + k0);
    CP_ASYNC16(s2u(&sB[0][r1][c1]), pB1 + k0);
    CP_COMMIT();

    for (int it = 0; it < iters; ++it) {
        if (it + 1 < iters) {
            int s = (it + 1) & 1;
            int kb = k0 + (it + 1) * 32;
            CP_ASYNC16(s2u(&sA[s][r0][c0]), pA0 + kb);
            CP_ASYNC16(s2u(&sA[s][r1][c1]), pA1 + kb);
            CP_ASYNC16(s2u(&sB[s][r0][c0]), pB0 + kb);
            CP_ASYNC16(s2u(&sB[s][r1][c1]), pB1 + kb);
            CP_COMMIT();
            CP_WAIT(1);
        } else {
            CP_WAIT(0);
        }
        __syncthreads();
        int cs = it & 1;
#pragma unroll
        for (int ks = 0; ks < 2; ks++) {
            int kk = ks * 16;
            uint32_t a[4][4], b[4][2];
#pragma unroll
            for (int mi = 0; mi < 4; mi++) {
                uint32_t addr = s2u(&sA[cs][wm + mi * 16 + (lane & 15)][kk + (lane >> 4) * 8]);
                asm volatile("ldmatrix.sync.aligned.m8n8.x4.shared.b16 {%0,%1,%2,%3}, [%4];"
                             : "=r"(a[mi][0]), "=r"(a[mi][1]), "=r"(a[mi][2]), "=r"(a[mi][3])
                             : "r"(addr));
            }
#pragma unroll
            for (int ni = 0; ni < 4; ni++) {
                int l = lane & 15;
                uint32_t addr = s2u(&sB[cs][wn + ni * 8 + (l & 7)][kk + (l >> 3) * 8]);
                asm volatile("ldmatrix.sync.aligned.m8n8.x2.shared.b16 {%0,%1}, [%2];"
                             : "=r"(b[ni][0]), "=r"(b[ni][1]) : "r"(addr));
            }
#pragma unroll
            for (int mi = 0; mi < 4; mi++)
#pragma unroll
                for (int ni = 0; ni < 4; ni++)
                    asm volatile(
                        "mma.sync.aligned.m16n8k16.row.col.f32.bf16.bf16.f32 "
                        "{%0,%1,%2,%3}, {%4,%5,%6,%7}, {%8,%9}, {%0,%1,%2,%3};"
                        : "+f"(c[mi][ni][0]), "+f"(c[mi][ni][1]),
                          "+f"(c[mi][ni][2]), "+f"(c[mi][ni][3])
                        : "r"(a[mi][0]), "r"(a[mi][1]), "r"(a[mi][2]), "r"(a[mi][3]),
                          "r"(b[ni][0]), "r"(b[ni][1]));
        }
        __syncthreads();
    }

#pragma unroll
    for (int mi = 0; mi < 4; mi++) {
        int row = bm + wm + mi * 16 + (lane >> 2);
#pragma unroll
        for (int ni = 0; ni < 4; ni++) {
            int col = bn + wn + ni * 8 + (lane & 3) * 2;
            *(float2*)(Cf + (size_t)row * ldc + col) =
                make_float2(c[mi][ni][0] * scale, c[mi][ni][1] * scale);
            *(float2*)(Cf + (size_t)(row + 8) * ldc + col) =
                make_float2(c[mi][ni][2] * scale, c[mi][ni][3] * scale);
        }
    }
}

// -- fused tail: combine split-K -> clause bits -> outputs -> sparse V -> final --
// one block per real window (BW); 256 threads
__global__ void __launch_bounds__(256)
combine_final_kernel(const float* __restrict__ b1,
                     const float* __restrict__ b2,
                     const float* __restrict__ xres,
                     const float* __restrict__ gate,
                     float* __restrict__ out_cl,
                     float* __restrict__ out_sum,
                     float* __restrict__ out) {
    __shared__ uint32_t slit[16];
    __shared__ int      swbase[8];
    __shared__ int      scount;
    __shared__ uint16_t sact[NCL];
    int row  = blockIdx.x;       // 0..BW-1
    int c    = threadIdx.x;      // 0..255  (feature, then clause)
    int wid  = c >> 5, lane = c & 31;
    if (c == 0) scount = 0;
    float s = b1[c];
#pragma unroll
    for (int z = 0; z < KSPL; z++) s += g_part[(size_t)z * MP * HID + (size_t)row * HID + c];
    uint32_t mp = __ballot_sync(0xffffffffu, s > 0.0f);
    uint32_t mn = __ballot_sync(0xffffffffu, s < 0.0f);
    if ((c & 31) == 0) {
        slit[c >> 5]       = mp;
        slit[8 + (c >> 5)] = mn;
    }
    __syncthreads();
    uint32_t viol = 0;
#pragma unroll
    for (int i = 0; i < 16; i++) viol |= g_incb[i * NCL + c] & ~slit[i];
    bool act = (viol == 0u);
    out_cl[(size_t)row * NCL + c] = act ? 1.0f : 0.0f;
    // compact active clause indices into shared
    uint32_t cm = __ballot_sync(0xffffffffu, act);
    if (lane == 0) swbase[wid] = atomicAdd(&scount, __popc(cm));
    __syncwarp();
    if (act) {
        int pos = swbase[wid] + __popc(cm & ((1u << lane) - 1u));
        sact[pos] = (uint16_t)c;
    }
    __syncthreads();
    int cnt = scount;
    if (c == 0) out_sum[row] = (float)cnt * (1.0f / NCL);

    // final: preact = b2 + sum_{active cl} V[cl]; window reverse + roll + gate
    int b  = row / (NWH * NWH);
    int r2 = row % (NWH * NWH);
    int wh = r2 / NWH, ww = r2 % NWH;
    float g = sigmoidf_(gate[0]);
#pragma unroll
    for (int j = 0; j < 12; j++) {
        int v    = c + j * 256;          // 0..3071 = wpos*192 + ch
        int wpos = v / C_;
        int ch   = v - wpos * C_;
        float acc = b2[v];
        for (int i = 0; i < cnt; i++)
            acc += g_V[(size_t)sact[i] * IND + v];
        float m = sigmoidf_(acc);
        int hr = wh * 4 + (wpos >> 2);
        int wr = ww * 4 + (wpos & 3);
        int h = hr + 2; if (h >= H_) h -= H_;
        int w = wr + 2; if (w >= W_) w -= W_;
        size_t pix = ((size_t)(b * H_ + h) * W_ + w) * C_ + ch;
        out[pix] = xres[pix] + g * m + (1.0f - g) * sigmoidf_(m);
    }
}

// ---------------- host launcher -----------------------------------------------
static void* sym_addr(const void* sym) {
    void* p = nullptr;
    cudaGetSymbolAddress(&p, sym);
    return p;
}

extern "C" void kernel_launch(void* const* d_in, const int* in_sizes, int n_in,
                              void* d_out, int out_size) {
    const float* x      = (const float*)d_in[0];
    const float* gamma  = (const float*)d_in[1];
    const float* beta   = (const float*)d_in[2];
    const float* W1     = (const float*)d_in[3];
    const float* b1     = (const float*)d_in[4];
    const float* inc_w  = (const float*)d_in[5];
    const float* vote_w = (const float*)d_in[6];
    const float* W2     = (const float*)d_in[7];
    const float* b2     = (const float*)d_in[8];
    const float* gate   = (const float*)d_in[9];

    float* out     = (float*)d_out;
    float* out_cl  = out + (size_t)B_ * H_ * W_ * C_;
    float* out_sum = out_cl + (size_t)BW * NCL;

    __nv_bfloat16* p_win  = (__nv_bfloat16*)sym_addr(g_win);
    __nv_bfloat16* p_W1T  = (__nv_bfloat16*)sym_addr(g_W1T);
    __nv_bfloat16* p_W2T  = (__nv_bfloat16*)sym_addr(g_W2T);
    __nv_bfloat16* p_vwb  = (__nv_bfloat16*)sym_addr(g_vwb);
    float*         p_V    = (float*)sym_addr(g_V);
    float*         p_part = (float*)sym_addr(g_part);

    // 1) fused: LN + roll + partition  AND  weight transposes + bitpack + vote bf16
    ln_prep_kernel<<<NB_LN + NB_PREP, 256>>>(x, gamma, beta, W1, W2, inc_w, vote_w);
    // 2a) V = (vote_w @ W2) / 16   (M=256, N=3072, K=192)
    mma_gemm1<<<dim3(24, 2, 1), 256>>>(p_vwb, C_, p_W2T, C_, p_V, IND, C_, 0, 0.0625f);
    // 2b) GEMM1 (split-K=6): partials = win @ W1   (156 CTAs ~ 1 wave)
    mma_gemm1<<<dim3(2, 13, KSPL), 256>>>(p_win, IND, p_W1T, IND,
                                          p_part, HID, IND / KSPL, MP * HID, 1.0f);
    // 3) fused tail: combine -> clause bits/outputs -> sparse V sum -> final out
    combine_final_kernel<<<BW, 256>>>(b1, b2, x, gate, out_cl, out_sum, out);
}